// round 11
// baseline (speedup 1.0000x reference)
#include <cuda_runtime.h>
#include <math_constants.h>

#define BB 8
#define NN 4096
#define NS 1024
#define SEGS 8
#define ROWS_PER_SEG 128          // NS / SEGS
#define STHREADS 512              // serial kernel block size

// Device scratch (no allocation allowed; __device__ globals are the escape hatch).
__device__ float4 g_p1[BB * NS];
__device__ float4 g_p2[BB * NS];
__device__ unsigned long long g_rowKey[BB * NS];
__device__ unsigned long long g_rowSec[BB * NS];
__device__ unsigned long long g_rowThird[BB * NS];
__device__ float g_batchLoss[BB];
__device__ unsigned g_done;

// Key layout: [63:32] d2 bits  [31:16] row id  [15:0] col id
// Lexicographic u64 order == reference's row-major (value,row,col) argmin order.
// Dead/invalid sentinel = ~0ULL.
#define MKKEY(vb, rid, cs) ((((unsigned long long)(vb)) << 32) | \
                            ((unsigned)(rid) << 16) | (unsigned)(cs))
#define PK2KEY(pk, rid) (((pk) == ~0ULL) ? ~0ULL : \
    MKKEY((unsigned)((pk) >> 10), (rid), (unsigned)((pk) & 0x3FFu)))

// ===================== init: chip-parallel best-3 per row =====================
__global__ __launch_bounds__(ROWS_PER_SEG, 1)
void emd_init_kernel(const float* __restrict__ S1,
                     const float* __restrict__ S2,
                     const int*   __restrict__ idxs) {
    __shared__ float4 p2s[NS];            // 16 KB

    const int seg = blockIdx.x;
    const int b   = blockIdx.y;
    const int t   = threadIdx.x;

    if (seg == 0 && b == 0 && t == 0) g_done = 0;   // reset finisher counter

    for (int i = t; i < NS; i += ROWS_PER_SEG) {
        int id = idxs[b * NS + i];
        const float* q2 = S2 + ((long)b * NN + id) * 3;
        float4 f = make_float4(q2[0], q2[1], q2[2], __int_as_float(i));
        p2s[i] = f;
        if (seg == 0) g_p2[b * NS + i] = f;
    }
    __syncthreads();

    const int row = seg * ROWS_PER_SEG + t;
    int id = idxs[b * NS + row];
    const float* q1 = S1 + ((long)b * NN + id) * 3;
    float4 p = make_float4(q1[0], q1[1], q1[2], 0.f);
    g_p1[b * NS + row] = p;

    float b1 = CUDART_INF_F, b2 = CUDART_INF_F, b3 = CUDART_INF_F;
    int   c1 = 0, c2 = 0, c3 = 0;
    #pragma unroll 4
    for (int c = 0; c < NS; ++c) {
        float4 q = p2s[c];
        float dx = p.x - q.x, dy = p.y - q.y, dz = p.z - q.z;
        float d2 = fmaf(dz, dz, fmaf(dy, dy, dx * dx));
        if (d2 < b3) {                        // strict <: lowest col on ties
            if (d2 < b2) { b3 = b2; c3 = c2;
                if (d2 < b1) { b2 = b1; c2 = c1; b1 = d2; c1 = c; }
                else         { b2 = d2; c2 = c; }
            } else { b3 = d2; c3 = c; }
        }
    }
    g_rowKey[b * NS + row]   = MKKEY(__float_as_uint(b1), row, c1);
    g_rowSec[b * NS + row]   = MKKEY(__float_as_uint(b2), row, c2);
    g_rowThird[b * NS + row] = MKKEY(__float_as_uint(b3), row, c3);
}

// ===================== serial: one warp per batch greedy chain ================
struct SmemLayout {
    float4 p1s[NS];                  // 16 KB
    float4 p2sC[NS];                 // 16 KB  compact; .w = col id
    unsigned long long rowKey[NS];   //  8 KB  best key (~0 = dead row)
    unsigned long long rowSec[NS];   //  8 KB
    unsigned long long rowThird[NS]; //  8 KB
    unsigned short colPos[NS];       //  2 KB
    unsigned char  colAlive[NS];     //  1 KB
};
#define SMEM_BYTES ((int)sizeof(SmemLayout))

__global__ __launch_bounds__(STHREADS, 1)
void emd_serial_kernel(float* __restrict__ out) {
    extern __shared__ char smem_raw[];
    SmemLayout* sm = reinterpret_cast<SmemLayout*>(smem_raw);
    float4* p1s  = sm->p1s;
    float4* p2sC = sm->p2sC;
    unsigned long long* rowKey   = sm->rowKey;
    unsigned long long* rowSec   = sm->rowSec;
    unsigned long long* rowThird = sm->rowThird;
    unsigned short* colPos = sm->colPos;
    unsigned char*  colAlive = sm->colAlive;

    const int b = blockIdx.x;
    const int t = threadIdx.x;

    // ---- reload precomputed state (contiguous, coalesced) ----
    for (int i = t; i < NS; i += STHREADS) {
        p1s[i]      = g_p1[b * NS + i];
        p2sC[i]     = g_p2[b * NS + i];
        rowKey[i]   = g_rowKey[b * NS + i];
        rowSec[i]   = g_rowSec[b * NS + i];
        rowThird[i] = g_rowThird[b * NS + i];
        colPos[i]   = (unsigned short)i;
        colAlive[i] = 1;
    }
    __syncthreads();

    if (t >= 32) return;   // single warp runs the sequential greedy chain

    const unsigned FULL = 0xffffffffu;
    const int lane = t;
    const int segBase = lane * 32;
    float loss = 0.f;

    // lane-local segment-min recompute: 4 independent accumulator chains
    auto segMin = [&]() -> unsigned long long {
        unsigned long long a0 = ~0ULL, a1 = ~0ULL, a2 = ~0ULL, a3 = ~0ULL;
        #pragma unroll
        for (int i = 0; i < 32; i += 4) {
            unsigned long long k0 = rowKey[segBase + i + 0];
            unsigned long long k1 = rowKey[segBase + i + 1];
            unsigned long long k2 = rowKey[segBase + i + 2];
            unsigned long long k3 = rowKey[segBase + i + 3];
            if (k0 < a0) a0 = k0;
            if (k1 < a1) a1 = k1;
            if (k2 < a2) a2 = k2;
            if (k3 < a3) a3 = k3;
        }
        unsigned long long m01 = (a0 < a1) ? a0 : a1;
        unsigned long long m23 = (a2 < a3) ? a2 : a3;
        return (m01 < m23) ? m01 : m23;
    };

    unsigned long long mySeg = segMin();

    for (int it = 0; it < NS; ++it) {
        const int nAlive = NS - it;

        // ======== validation phase: repair stale segment minima IN PARALLEL ====
        for (;;) {
            bool invalid = (mySeg != ~0ULL) &&
                           !colAlive[(int)(mySeg & 0xFFFFu)];
            if (!__ballot_sync(FULL, invalid)) break;

            bool needRescan = false;
            int  myRow = 0;
            if (invalid) {
                // lane-local promotion (no warp collectives)
                int rid = (int)((mySeg >> 16) & 0xFFFFu);
                myRow = rid;
                unsigned long long sec = rowSec[rid];
                unsigned long long thr = rowThird[rid];
                bool secOk = (sec != ~0ULL) && colAlive[(int)(sec & 0xFFFFu)];
                if (secOk) {
                    rowKey[rid] = sec; rowSec[rid] = thr; rowThird[rid] = ~0ULL;
                } else {
                    bool thrOk = (thr != ~0ULL) && colAlive[(int)(thr & 0xFFFFu)];
                    if (thrOk) {
                        rowKey[rid] = thr; rowSec[rid] = ~0ULL; rowThird[rid] = ~0ULL;
                    } else {
                        needRescan = true;
                    }
                }
            }

            // warp-cooperative rescans for exhausted rows (rare)
            unsigned resc = __ballot_sync(FULL, needRescan);
            while (resc) {
                int src = __ffs(resc) - 1; resc &= resc - 1;
                int rr = __shfl_sync(FULL, myRow, src);
                float4 p = p1s[rr];
                unsigned long long k0 = ~0ULL, k1 = ~0ULL, k2 = ~0ULL;
                #pragma unroll 4
                for (int j = lane; j < nAlive; j += 32) {
                    float4 q = p2sC[j];
                    float dx = p.x - q.x, dy = p.y - q.y, dz = p.z - q.z;
                    float d2 = fmaf(dz, dz, fmaf(dy, dy, dx * dx));
                    unsigned long long k =
                        (((unsigned long long)__float_as_uint(d2)) << 10) |
                        (unsigned)__float_as_int(q.w);
                    if (k < k2) {
                        if (k < k1) { k2 = k1;
                            if (k < k0) { k1 = k0; k0 = k; } else k1 = k;
                        } else k2 = k;
                    }
                }
                #pragma unroll
                for (int off = 16; off > 0; off >>= 1) {   // top-3 butterfly
                    unsigned long long b0 = __shfl_xor_sync(FULL, k0, off);
                    unsigned long long b1 = __shfl_xor_sync(FULL, k1, off);
                    unsigned long long b2 = __shfl_xor_sync(FULL, k2, off);
                    unsigned long long t0 = (k0 < b2) ? k0 : b2;
                    unsigned long long t1 = (k1 < b1) ? k1 : b1;
                    unsigned long long t2 = (k2 < b0) ? k2 : b0;
                    unsigned long long s0 = (t0 < t1) ? t0 : t1;
                    unsigned long long s1 = (t0 < t1) ? t1 : t0;
                    unsigned long long s2 = (s1 < t2) ? t2 : s1;
                    s1 = (s1 < t2) ? s1 : t2;
                    k0 = (s0 < s1) ? s0 : s1;
                    k1 = (s0 < s1) ? s1 : s0;
                    k2 = s2;
                }
                if (lane == 0) {
                    rowKey[rr]   = PK2KEY(k0, rr);
                    rowSec[rr]   = PK2KEY(k1, rr);
                    rowThird[rr] = PK2KEY(k2, rr);
                }
            }
            __syncwarp(FULL);   // writes -> segMin reads

            if (invalid) mySeg = segMin();   // parallel across invalid lanes
        }

        // ======== global pop: all 32 segment minima are exact ====
        unsigned hi  = (unsigned)(mySeg >> 32);
        unsigned lo  = (unsigned)mySeg;
        unsigned mhi = __reduce_min_sync(FULL, hi);
        unsigned mlo = __reduce_min_sync(FULL, (hi == mhi) ? lo : 0xFFFFFFFFu);
        float v  = __uint_as_float(mhi);
        int rid  = (int)(mlo >> 16);
        int csel = (int)(mlo & 0xFFFFu);

        // ======== accept: kill row (sentinel) + swap-remove col ====
        const int lastP = nAlive - 1;
        float4 fLast = p2sC[lastP];           // independent broadcast loads
        int cpos = colPos[csel];
        if (lane == 0) {
            loss += sqrtf(v);                 // reference accumulation order
            rowKey[rid] = ~0ULL;
            p2sC[cpos] = fLast;               // col id rides in .w
            colPos[(unsigned)__float_as_int(fLast.w)] = (unsigned short)cpos;
            colAlive[csel] = 0;
        }
        __syncwarp(FULL);
        if (lane == (rid >> 5)) mySeg = segMin();   // only owner recomputes
    }

    // ======== deterministic finisher: last block sums in fixed order ====
    if (lane == 0) {
        g_batchLoss[b] = loss / (float)NS;
        __threadfence();
        unsigned old = atomicAdd(&g_done, 1u);
        if (old == BB - 1) {
            float s = 0.f;
            #pragma unroll
            for (int i = 0; i < BB; ++i) s += g_batchLoss[i];
            out[0] = s / (float)BB;
        }
    }
}

extern "C" void kernel_launch(void* const* d_in, const int* in_sizes, int n_in,
                              void* d_out, int out_size) {
    const float* S1  = (const float*)d_in[0];
    const float* S2  = (const float*)d_in[1];
    const int*   idx = (const int*)  d_in[2];
    float* out = (float*)d_out;

    // Opt in to >48KB dynamic shared memory (non-stream API: immediate,
    // alloc-free, idempotent — safe under graph capture).
    cudaFuncSetAttribute(emd_serial_kernel,
                         cudaFuncAttributeMaxDynamicSharedMemorySize, SMEM_BYTES);

    emd_init_kernel<<<dim3(SEGS, BB), ROWS_PER_SEG>>>(S1, S2, idx);
    emd_serial_kernel<<<BB, STHREADS, SMEM_BYTES>>>(out);
}

// round 13
// speedup vs baseline: 1.8486x; 1.8486x over previous
#include <cuda_runtime.h>
#include <math_constants.h>

#define BB 8
#define NN 4096
#define NS 1024
#define SEGS 8
#define ROWS_PER_SEG 128          // NS / SEGS
#define STHREADS 512              // serial kernel block size

// Device scratch (no allocation allowed; __device__ globals are the escape hatch).
__device__ float4 g_p1[BB * NS];
__device__ float4 g_p2[BB * NS];
__device__ unsigned long long g_rowKey[BB * NS];
__device__ unsigned long long g_rowSec[BB * NS];
__device__ float g_batchLoss[BB];
__device__ unsigned g_done;

// Key layout: [63:32] d2 bits  [31:16] row id  [15:0] col id
// Lexicographic u64 order == reference's row-major (value,row,col) argmin order.
// Dead/invalid sentinel = ~0ULL.
#define MKKEY(vb, rid, cs) ((((unsigned long long)(vb)) << 32) | \
                            ((unsigned)(rid) << 16) | (unsigned)(cs))

// ===================== init: chip-parallel best-2 per row =====================
__global__ __launch_bounds__(ROWS_PER_SEG, 1)
void emd_init_kernel(const float* __restrict__ S1,
                     const float* __restrict__ S2,
                     const int*   __restrict__ idxs) {
    __shared__ float4 p2s[NS];            // 16 KB

    const int seg = blockIdx.x;
    const int b   = blockIdx.y;
    const int t   = threadIdx.x;

    if (seg == 0 && b == 0 && t == 0) g_done = 0;   // reset finisher counter

    for (int i = t; i < NS; i += ROWS_PER_SEG) {
        int id = idxs[b * NS + i];
        const float* q2 = S2 + ((long)b * NN + id) * 3;
        float4 f = make_float4(q2[0], q2[1], q2[2], __int_as_float(i));
        p2s[i] = f;
        if (seg == 0) g_p2[b * NS + i] = f;   // one block persists the col points
    }
    __syncthreads();

    const int row = seg * ROWS_PER_SEG + t;
    int id = idxs[b * NS + row];
    const float* q1 = S1 + ((long)b * NN + id) * 3;
    float4 p = make_float4(q1[0], q1[1], q1[2], 0.f);
    g_p1[b * NS + row] = p;

    float b1 = CUDART_INF_F, b2 = CUDART_INF_F;
    int   c1 = 0, c2 = 0;
    #pragma unroll 4
    for (int c = 0; c < NS; ++c) {            // uniform c -> LDS broadcast
        float4 q = p2s[c];
        float dx = p.x - q.x, dy = p.y - q.y, dz = p.z - q.z;
        float d2 = fmaf(dz, dz, fmaf(dy, dy, dx * dx));
        if (d2 < b1)      { b2 = b1; c2 = c1; b1 = d2; c1 = c; }
        else if (d2 < b2) { b2 = d2; c2 = c; }   // strict <: lowest col on ties
    }
    g_rowKey[b * NS + row] = MKKEY(__float_as_uint(b1), row, c1);
    g_rowSec[b * NS + row] = MKKEY(__float_as_uint(b2), row, c2);
}

// ===================== serial: one warp per batch greedy chain ================
struct SmemLayout {
    float4 p1s[NS];                  // 16 KB
    float4 p2sC[NS];                 // 16 KB  compact; .w = col id
    unsigned long long rowKey[NS];   //  8 KB  best key (~0 = dead row)
    unsigned long long rowSec[NS];   //  8 KB  2nd-best key (~0 = invalid)
    unsigned short colPos[NS];       //  2 KB
    unsigned char  colAlive[NS];     //  1 KB
};
#define SMEM_BYTES ((int)sizeof(SmemLayout))

__global__ __launch_bounds__(STHREADS, 1)
void emd_serial_kernel(float* __restrict__ out) {
    extern __shared__ char smem_raw[];
    SmemLayout* sm = reinterpret_cast<SmemLayout*>(smem_raw);
    float4* p1s  = sm->p1s;
    float4* p2sC = sm->p2sC;
    unsigned long long* rowKey = sm->rowKey;
    unsigned long long* rowSec = sm->rowSec;
    unsigned short* colPos = sm->colPos;
    unsigned char*  colAlive = sm->colAlive;

    const int b = blockIdx.x;
    const int t = threadIdx.x;

    // ---- reload precomputed state (contiguous, coalesced) ----
    for (int i = t; i < NS; i += STHREADS) {
        p1s[i]    = g_p1[b * NS + i];
        p2sC[i]   = g_p2[b * NS + i];
        rowKey[i] = g_rowKey[b * NS + i];
        rowSec[i] = g_rowSec[b * NS + i];
        colPos[i]   = (unsigned short)i;
        colAlive[i] = 1;
    }
    __syncthreads();

    if (t >= 32) return;   // single warp runs the sequential greedy chain

    const unsigned FULL = 0xffffffffu;
    const int lane = t;
    float loss = 0.f;

    // ---- register-resident segment minima: lane owns rows [lane*32, +32) ----
    unsigned long long mySeg;
    {
        unsigned long long a0 = ~0ULL, a1 = ~0ULL, a2 = ~0ULL, a3 = ~0ULL;
        #pragma unroll
        for (int i = 0; i < 32; i += 4) {     // 4 independent chains
            unsigned long long k0 = rowKey[lane * 32 + i + 0];
            unsigned long long k1 = rowKey[lane * 32 + i + 1];
            unsigned long long k2 = rowKey[lane * 32 + i + 2];
            unsigned long long k3 = rowKey[lane * 32 + i + 3];
            if (k0 < a0) a0 = k0;
            if (k1 < a1) a1 = k1;
            if (k2 < a2) a2 = k2;
            if (k3 < a3) a3 = k3;
        }
        unsigned long long m01 = (a0 < a1) ? a0 : a1;
        unsigned long long m23 = (a2 < a3) ? a2 : a3;
        mySeg = (m01 < m23) ? m01 : m23;
    }

    for (int it = 0; it < NS; ++it) {
        const int nAlive = NS - it;
        int rid, csel;
        float v;

        for (;;) {
            // ---- O(1) global lexmin over 32 register segment minima ----
            unsigned hi  = (unsigned)(mySeg >> 32);
            unsigned lo  = (unsigned)mySeg;
            unsigned mhi = __reduce_min_sync(FULL, hi);
            unsigned mlo = __reduce_min_sync(FULL, (hi == mhi) ? lo : 0xFFFFFFFFu);
            rid  = (int)(mlo >> 16);
            csel = (int)(mlo & 0xFFFFu);

            if (colAlive[csel]) { v = __uint_as_float(mhi); break; }

            const int seg = rid >> 5;

            // ---- speculative broadcast load (uniform LDS, issued early) ----
            unsigned long long sec = rowSec[rid];
            bool prom = (sec != ~0ULL) && colAlive[(int)(sec & 0xFFFFu)];

            if (prom) {
                // promote second-best: uniform branch, no shuffles
                if (lane == 0) { rowKey[rid] = sec; rowSec[rid] = ~0ULL; }
            } else {
                // ---- full rescan of row rid over alive cols; refill best-2 ----
                float4 p = p1s[rid];
                unsigned long long kb1 = ~0ULL, kb2 = ~0ULL;
                #pragma unroll 4
                for (int j = lane; j < nAlive; j += 32) {
                    float4 q = p2sC[j];
                    float dx = p.x - q.x, dy = p.y - q.y, dz = p.z - q.z;
                    float d2 = fmaf(dz, dz, fmaf(dy, dy, dx * dx));
                    unsigned long long k =
                        (((unsigned long long)__float_as_uint(d2)) << 10) |
                        (unsigned)__float_as_int(q.w);
                    if (k < kb1)      { kb2 = kb1; kb1 = k; }
                    else if (k < kb2) { kb2 = k; }
                }
                #pragma unroll
                for (int off = 16; off > 0; off >>= 1) {   // butterfly best-2
                    unsigned long long o1 = __shfl_xor_sync(FULL, kb1, off);
                    unsigned long long o2 = __shfl_xor_sync(FULL, kb2, off);
                    unsigned long long n1 = (o1 < kb1) ? o1 : kb1;
                    unsigned long long mx = (o1 < kb1) ? kb1 : o1;
                    unsigned long long n2 = (o2 < kb2) ? o2 : kb2;
                    kb1 = n1; kb2 = (mx < n2) ? mx : n2;
                }
                if (lane == 0) {
                    rowKey[rid] = MKKEY((unsigned)(kb1 >> 10), rid,
                                        (unsigned)(kb1 & 0x3FFu));
                    rowSec[rid] = (kb2 == ~0ULL) ? ~0ULL
                        : MKKEY((unsigned)(kb2 >> 10), rid, (unsigned)(kb2 & 0x3FFu));
                }
            }
            __syncwarp(FULL);   // lane0 writes -> all-lane reads below

            // ---- warp-cooperative segment recompute: 1 LDS.64 per lane ----
            unsigned long long kk = rowKey[seg * 32 + lane];
            unsigned h2 = (unsigned)(kk >> 32), l2 = (unsigned)kk;
            unsigned m2 = __reduce_min_sync(FULL, h2);
            unsigned n2 = __reduce_min_sync(FULL, (h2 == m2) ? l2 : 0xFFFFFFFFu);
            if (lane == seg) mySeg = (((unsigned long long)m2) << 32) | n2;
            // no syncwarp: next selection is register-only convergent collectives
        }

        // ---- accept (rid, csel, v): kill row (sentinel) + swap-remove col ----
        {
            const int seg = rid >> 5;
            const int lastP = nAlive - 1;
            float4 fLast = p2sC[lastP];           // independent broadcast loads
            int cpos = colPos[csel];
            if (lane == 0) {
                loss += sqrtf(v);                 // reference accumulation order
                rowKey[rid] = ~0ULL;
                p2sC[cpos] = fLast;               // col id rides in .w
                colPos[(unsigned)__float_as_int(fLast.w)] = (unsigned short)cpos;
                colAlive[csel] = 0;
            }
            __syncwarp(FULL);                     // writes -> seg-recompute reads
            unsigned long long kk = rowKey[seg * 32 + lane];
            unsigned h2 = (unsigned)(kk >> 32), l2 = (unsigned)kk;
            unsigned m2 = __reduce_min_sync(FULL, h2);
            unsigned n2 = __reduce_min_sync(FULL, (h2 == m2) ? l2 : 0xFFFFFFFFu);
            if (lane == seg) mySeg = (((unsigned long long)m2) << 32) | n2;
        }
    }

    // ---- deterministic finisher: last block sums in fixed order ----
    if (lane == 0) {
        g_batchLoss[b] = loss / (float)NS;
        __threadfence();
        unsigned old = atomicAdd(&g_done, 1u);
        if (old == BB - 1) {
            float s = 0.f;
            #pragma unroll
            for (int i = 0; i < BB; ++i) s += g_batchLoss[i];
            out[0] = s / (float)BB;
        }
    }
}

extern "C" void kernel_launch(void* const* d_in, const int* in_sizes, int n_in,
                              void* d_out, int out_size) {
    const float* S1  = (const float*)d_in[0];
    const float* S2  = (const float*)d_in[1];
    const int*   idx = (const int*)  d_in[2];
    float* out = (float*)d_out;

    // Opt in to >48KB dynamic shared memory (non-stream API: immediate,
    // alloc-free, idempotent — safe under graph capture).
    cudaFuncSetAttribute(emd_serial_kernel,
                         cudaFuncAttributeMaxDynamicSharedMemorySize, SMEM_BYTES);

    emd_init_kernel<<<dim3(SEGS, BB), ROWS_PER_SEG>>>(S1, S2, idx);
    emd_serial_kernel<<<BB, STHREADS, SMEM_BYTES>>>(out);
}